// round 5
// baseline (speedup 1.0000x reference)
#include <cuda_runtime.h>

namespace {
constexpr int NX = 256, NY = 256, NZ = 128;
constexpr int NZ2 = NZ / 2;            // 64 float2 per z-line
constexpr int XS2 = NY * NZ2;
constexpr int FS2 = NX * XS2;
constexpr int BY  = 4;                 // y rows per block

constexpr float CVc = 717.0f;
constexpr float MUc = 1.8e-5f, KTHc = 0.025f, Gc = 9.8f;
constexpr float Rg  = 287.0f;

constexpr double DXd = 1.0 / NX, DYd = 1.0 / NY, DZd = 1.0 / (NZ - 1);
constexpr float inv2dx = (float)(0.5 / DXd);
constexpr float inv2dy = (float)(0.5 / DYd);
constexpr float inv2dz = (float)(0.5 / DZd);
constexpr float invdx2 = (float)(1.0 / (DXd * DXd));
constexpr float invdy2 = (float)(1.0 / (DYd * DYd));
constexpr float invdz2 = (float)(1.0 / (DZd * DZd));
constexpr float kTco   = KTHc / CVc;

__device__ __forceinline__ float2 operator+(float2 a, float2 b){ return make_float2(a.x+b.x, a.y+b.y); }
__device__ __forceinline__ float2 operator-(float2 a, float2 b){ return make_float2(a.x-b.x, a.y-b.y); }
__device__ __forceinline__ float2 operator*(float2 a, float2 b){ return make_float2(a.x*b.x, a.y*b.y); }
__device__ __forceinline__ float2 operator*(float2 a, float s){ return make_float2(a.x*s, a.y*s); }
__device__ __forceinline__ float2 operator*(float s, float2 a){ return a * s; }

// z-1 vector {prev.y, a.x}; at the warp seam (tz==32) the low element comes from smem patch
__device__ __forceinline__ float2 zmv(float2 a, float patch, bool p){
    float t = __shfl_up_sync(0xffffffffu, a.y, 1);
    return make_float2(p ? patch : t, a.x);
}
// z+1 vector {a.y, next.x}; at the warp seam (tz==31) the high element comes from smem patch
__device__ __forceinline__ float2 zpv(float2 a, float patch, bool p){
    float t = __shfl_down_sync(0xffffffffu, a.x, 1);
    return make_float2(a.y, p ? patch : t);
}

__device__ __forceinline__ float2 maskwall(float2 v, bool lo, bool hi){
    if (lo) v.x = 0.0f;
    if (hi) v.y = 0.0f;
    return v;
}

__global__ __launch_bounds__(256, 4)
void rb2_kernel(const float2* __restrict__ s, float2* __restrict__ o)
{
    const int tz = threadIdx.x;                         // 0..63 : 2 z per thread
    const int ty = threadIdx.y;                         // 0..3
    const int y  = blockIdx.x * BY + ty;
    const int x  = blockIdx.y;

    const int rowc = y * NZ2 + tz;
    const int ic  = x * XS2 + rowc;
    const int ixm = ((x + NX - 1) & (NX - 1)) * XS2 + rowc;
    const int ixp = ((x + 1)      & (NX - 1)) * XS2 + rowc;
    const int iym = x * XS2 + ((y + NY - 1) & (NY - 1)) * NZ2 + tz;
    const int iyp = x * XS2 + ((y + 1)      & (NY - 1)) * NZ2 + tz;

    const bool lo = (tz == 0);         // z = 0
    const bool hi = (tz == 63);        // z = 127
    const bool seamLo = (tz == 32);    // needs z=63 patch for zm
    const bool seamHi = (tz == 31);    // needs z=64 patch for zp

    __shared__ float eLo[BY][6];       // z=63 value (from tz==31 .y)
    __shared__ float eHi[BY][6];       // z=64 value (from tz==32 .x)

    // centers (all 6 fields, persistent)
    const float2 uc = s[0 * FS2 + ic];
    const float2 vc = s[1 * FS2 + ic];
    const float2 wc = s[2 * FS2 + ic];
    const float2 rc = s[3 * FS2 + ic];
    const float2 Tc = s[4 * FS2 + ic];
    const float2 cc = s[5 * FS2 + ic];

    if (tz == 31) { eLo[ty][0]=uc.y; eLo[ty][1]=vc.y; eLo[ty][2]=wc.y; eLo[ty][3]=rc.y; eLo[ty][4]=Tc.y; eLo[ty][5]=cc.y; }
    if (tz == 32) { eHi[ty][0]=uc.x; eHi[ty][1]=vc.x; eHi[ty][2]=wc.x; eHi[ty][3]=rc.x; eHi[ty][4]=Tc.x; eHi[ty][5]=cc.x; }
    __syncthreads();

    const float2 rinv = make_float2(1.0f / rc.x, 1.0f / rc.y);

    // ---- phase 1: rho & T → dT + pressure gradients ----
    const float2 rxm = s[3 * FS2 + ixm], rxp = s[3 * FS2 + ixp];
    float2 dpdx, dpdy, dpdz;
    {
        const float2 rym = s[3 * FS2 + iym], ryp = s[3 * FS2 + iyp];
        const float2 Txm = s[4 * FS2 + ixm], Txp = s[4 * FS2 + ixp];
        const float2 Tym = s[4 * FS2 + iym], Typ = s[4 * FS2 + iyp];
        const float2 rzm = zmv(rc, eLo[ty][3], seamLo), rzp = zpv(rc, eHi[ty][3], seamHi);
        const float2 Tzm = zmv(Tc, eLo[ty][4], seamLo), Tzp = zpv(Tc, eHi[ty][4], seamHi);

        dpdx = (rxp * Txp - rxm * Txm) * (Rg * inv2dx);
        dpdy = (ryp * Typ - rym * Tym) * (Rg * inv2dy);
        dpdz = (rzp * Tzp - rzm * Tzm) * (Rg * inv2dz);

        const float2 lapT = (Txp + Txm - Tc * 2.0f) * invdx2 + (Typ + Tym - Tc * 2.0f) * invdy2 + (Tzp + Tzm - Tc * 2.0f) * invdz2;
        const float2 advT = uc * ((Txp - Txm) * inv2dx) + vc * ((Typ - Tym) * inv2dy) + wc * ((Tzp - Tzm) * inv2dz);
        __stcs(&o[4 * FS2 + ic], maskwall((lapT * kTco) * rinv - advT, lo, hi));
    }

    // ---- phase 2: u (+ drou) ----
    {
        const float2 uxm = s[0 * FS2 + ixm], uxp = s[0 * FS2 + ixp];
        const float2 uym = s[0 * FS2 + iym], uyp = s[0 * FS2 + iyp];
        const float2 uzm = zmv(uc, eLo[ty][0], seamLo), uzp = zpv(uc, eHi[ty][0], seamHi);

        __stcs(&o[3 * FS2 + ic], (rxm * uxm - rxp * uxp) * inv2dx);

        const float2 lapU = (uxp + uxm - uc * 2.0f) * invdx2 + (uyp + uym - uc * 2.0f) * invdy2 + (uzp + uzm - uc * 2.0f) * invdz2;
        const float2 advU = uc * ((uxp - uxm) * inv2dx) + vc * ((uyp - uym) * inv2dy) + wc * ((uzp - uzm) * inv2dz);
        __stcs(&o[0 * FS2 + ic], maskwall((lapU * MUc - dpdx) * rinv - advU, lo, hi));
    }

    // ---- phase 3: v ----
    {
        const float2 vxm = s[1 * FS2 + ixm], vxp = s[1 * FS2 + ixp];
        const float2 vym = s[1 * FS2 + iym], vyp = s[1 * FS2 + iyp];
        const float2 vzm = zmv(vc, eLo[ty][1], seamLo), vzp = zpv(vc, eHi[ty][1], seamHi);
        const float2 lapV = (vxp + vxm - vc * 2.0f) * invdx2 + (vyp + vym - vc * 2.0f) * invdy2 + (vzp + vzm - vc * 2.0f) * invdz2;
        const float2 advV = uc * ((vxp - vxm) * inv2dx) + vc * ((vyp - vym) * inv2dy) + wc * ((vzp - vzm) * inv2dz);
        __stcs(&o[1 * FS2 + ic], maskwall((lapV * MUc - dpdy) * rinv - advV, lo, hi));
    }

    // ---- phase 4: w  ((-G*rho)/rho == -G) ----
    {
        const float2 wxm = s[2 * FS2 + ixm], wxp = s[2 * FS2 + ixp];
        const float2 wym = s[2 * FS2 + iym], wyp = s[2 * FS2 + iyp];
        const float2 wzm = zmv(wc, eLo[ty][2], seamLo), wzp = zpv(wc, eHi[ty][2], seamHi);
        const float2 lapW = (wxp + wxm - wc * 2.0f) * invdx2 + (wyp + wym - wc * 2.0f) * invdy2 + (wzp + wzm - wc * 2.0f) * invdz2;
        const float2 advW = uc * ((wxp - wxm) * inv2dx) + vc * ((wyp - wym) * inv2dy) + wc * ((wzp - wzm) * inv2dz);
        float2 dw = (lapW * MUc - dpdz) * rinv - advW;
        dw = make_float2(dw.x - Gc, dw.y - Gc);
        __stcs(&o[2 * FS2 + ic], maskwall(dw, lo, hi));
    }

    // ---- phase 5: c (one-sided z at walls, NOT masked) ----
    {
        const float2 cxm = s[5 * FS2 + ixm], cxp = s[5 * FS2 + ixp];
        const float2 cym = s[5 * FS2 + iym], cyp = s[5 * FS2 + iyp];
        const float2 czm = zmv(cc, eLo[ty][5], seamLo), czp = zpv(cc, eHi[ty][5], seamHi);

        float2 dcdz = (czp - czm) * inv2dz;
        if (lo) dcdz.x = (-3.0f * cc.x + 4.0f * cc.y - czp.y) * inv2dz;   // z=0: uses z1 (cc.y), z2 (czp.y)
        if (hi) dcdz.y = ( 3.0f * cc.y - 4.0f * cc.x + czm.x) * inv2dz;   // z=127: uses z126 (cc.x), z125 (czm.x)

        const float2 advC = uc * ((cxp - cxm) * inv2dx) + vc * ((cyp - cym) * inv2dy) + wc * dcdz;
        __stcs(&o[5 * FS2 + ic], make_float2(-advC.x, -advC.y));
    }
}
} // namespace

extern "C" void kernel_launch(void* const* d_in, const int* in_sizes, int n_in,
                              void* d_out, int out_size)
{
    const float2* s = (const float2*)d_in[0];
    float2* o = (float2*)d_out;
    dim3 block(NZ2, BY, 1);                 // 64 × 4 = 256 threads
    dim3 grid(NY / BY, NX, 1);              // 64 × 256 blocks
    rb2_kernel<<<grid, block>>>(s, o);
}